// round 8
// baseline (speedup 1.0000x reference)
#include <cuda_runtime.h>
#include <math.h>

// Problem constants (fixed by setup_inputs)
#define C_IN   64
#define C_OUT  128
#define NPAIR  2048            // B*T = 16*128
#define NCP    32              // c-pairs = C_IN/2

#define THREADS 128            // 4 pairs (1/warp) x 32 o-pairs (2 o per thread)
#define PAIRS_PER_BLOCK 4
#define W4S 33                 // padded float4 stride for weight quads

__device__ __forceinline__ float fsin_ap(float a) {
    float r; asm("sin.approx.f32 %0, %1;" : "=f"(r) : "f"(a)); return r;
}
__device__ __forceinline__ float fcos_ap(float a) {
    float r; asm("cos.approx.f32 %0, %1;" : "=f"(r) : "f"(a)); return r;
}
__device__ __forceinline__ float frcp_ap(float a) {
    float r; asm("rcp.approx.f32 %0, %1;" : "=f"(r) : "f"(a)); return r;
}

__global__ __launch_bounds__(THREADS, 7)
void qpu_kernel(const float* __restrict__ x,      // (NPAIR, 4*C_IN) [r|i|j|k]
                const float* __restrict__ weight, // (C_OUT, C_IN)
                const float* __restrict__ bias,   // (C_OUT)
                float* __restrict__ out)          // (NPAIR, 4*C_OUT)
{
    // Pairwise-combined preprocess per (pair, c-pair):
    //   A = {th01, v1x, v1y, v1z}   B = {th02, v2x, v2y, v2z}   C = {v1.v2, (v1 x v2)}
    __shared__ float4 pcA[PAIRS_PER_BLOCK][NCP];
    __shared__ float4 pcB[PAIRS_PER_BLOCK][NCP];
    __shared__ float4 pcC[PAIRS_PER_BLOCK][NCP];
    // weight quads: w4_s[cp*33+oh] = {w(o0,c1), w(o0,c2), w(o1,c1), w(o1,c2)}
    __shared__ float4 w4_s[NCP * W4S];

    const int tid   = threadIdx.x;
    const int p0    = blockIdx.x * PAIRS_PER_BLOCK;
    const int obase = blockIdx.y * 64;        // this block covers o in [obase, obase+64)

    // ---- stage weight quads (coalesced global reads, scalar scatter to shared) ----
    #pragma unroll
    for (int idx = tid; idx < 64 * C_IN; idx += THREADS) {
        int ol = idx >> 6;        // local o 0..63
        int c  = idx & 63;
        float v = weight[(obase + ol) * C_IN + c];
        int cp   = c >> 1;
        int comp = ((ol & 1) << 1) | (c & 1);
        ((float*)&w4_s[cp * W4S + (ol >> 1)])[comp] = v;
    }

    // ---- per-(pair, c-pair) preprocessing: one thread per item ----
    {
        int pp = tid >> 5;        // 0..3
        int cp = tid & 31;
        const float* xr = x + (size_t)(p0 + pp) * (4 * C_IN);
        int c1 = 2 * cp, c2 = 2 * cp + 1;
        const float CL = 1.0f - 1e-6f;

        float r1 = xr[c1], i1 = xr[C_IN + c1], j1 = xr[2*C_IN + c1], k1 = xr[3*C_IN + c1];
        float r2 = xr[c2], i2 = xr[C_IN + c2], j2 = xr[2*C_IN + c2], k2 = xr[3*C_IN + c2];

        float n1 = rsqrtf(fmaf(i1, i1, fmaf(j1, j1, fmaf(k1, k1, 1e-12f))));
        float n2 = rsqrtf(fmaf(i2, i2, fmaf(j2, j2, fmaf(k2, k2, 1e-12f))));
        float t01 = acosf(fminf(fmaxf(r1, -CL), CL));
        float t02 = acosf(fminf(fmaxf(r2, -CL), CL));

        float ax = i1 * n1, ay = j1 * n1, az = k1 * n1;
        float bx = i2 * n2, by = j2 * n2, bz = k2 * n2;
        float d  = fmaf(ax, bx, fmaf(ay, by, az * bz));
        float cx = fmaf(ay, bz, -az * by);
        float cy = fmaf(az, bx, -ax * bz);
        float cz = fmaf(ax, by, -ay * bx);

        pcA[pp][cp] = make_float4(t01, ax, ay, az);
        pcB[pp][cp] = make_float4(t02, bx, by, bz);
        pcC[pp][cp] = make_float4(d, cx, cy, cz);
    }
    __syncthreads();

    // ---- main loop: one thread = (one pair, two o-chains), c-pairs combined ----
    const int pp = tid >> 5;
    const int oh = tid & 31;
    const float2 b2 = ((const float2*)bias)[blockIdx.y * 32 + oh];

    float ar0, ai0, aj0, ak0, ar1, ai1, aj1, ak1;

    // macro-free inline: compute pairwise quaternion for one chain
    #define QPAIR(WA, WB, BB, QR, QX, QY, QZ)                                   \
        {                                                                       \
            float th1 = fmaf((WA), A.x, (BB));                                  \
            float th2 = fmaf((WB), B.x, (BB));                                  \
            float t1  = fsin_ap(th1) * frcp_ap(fcos_ap(th1));                   \
            float t2  = fsin_ap(th2) * frcp_ap(fcos_ap(th2));                   \
            float t12 = t1 * t2;                                                \
            QR = fmaf(-t12, C.x, 1.0f);                                         \
            QX = fmaf(t12, C.y, fmaf(t2, B.y, t1 * A.y));                       \
            QY = fmaf(t12, C.z, fmaf(t2, B.z, t1 * A.z));                       \
            QZ = fmaf(t12, C.w, fmaf(t2, B.w, t1 * A.w));                       \
        }

    // peel cp = 0: acc = q_pair0
    {
        float4 A = pcA[pp][0];
        float4 B = pcB[pp][0];
        float4 C = pcC[pp][0];
        float4 w = w4_s[oh];
        QPAIR(w.x, w.y, b2.x, ar0, ai0, aj0, ak0);
        QPAIR(w.z, w.w, b2.y, ar1, ai1, aj1, ak1);
    }

    #pragma unroll 4
    for (int cp = 1; cp < NCP; ++cp) {
        float4 A = pcA[pp][cp];
        float4 B = pcB[pp][cp];
        float4 C = pcC[pp][cp];
        float4 w = w4_s[cp * W4S + oh];

        float qr, qx, qy, qz;

        // chain 0
        QPAIR(w.x, w.y, b2.x, qr, qx, qy, qz);
        {
            float nr = ar0 * qr; nr = fmaf(-ai0, qx, nr); nr = fmaf(-aj0, qy, nr); nr = fmaf(-ak0, qz, nr);
            float ni = ar0 * qx; ni = fmaf( ai0, qr, ni); ni = fmaf( aj0, qz, ni); ni = fmaf(-ak0, qy, ni);
            float nj = ar0 * qy; nj = fmaf(-ai0, qz, nj); nj = fmaf( aj0, qr, nj); nj = fmaf( ak0, qx, nj);
            float nk = ar0 * qz; nk = fmaf( ai0, qy, nk); nk = fmaf(-aj0, qx, nk); nk = fmaf( ak0, qr, nk);
            ar0 = nr; ai0 = ni; aj0 = nj; ak0 = nk;
        }

        // chain 1
        QPAIR(w.z, w.w, b2.y, qr, qx, qy, qz);
        {
            float nr = ar1 * qr; nr = fmaf(-ai1, qx, nr); nr = fmaf(-aj1, qy, nr); nr = fmaf(-ak1, qz, nr);
            float ni = ar1 * qx; ni = fmaf( ai1, qr, ni); ni = fmaf( aj1, qz, ni); ni = fmaf(-ak1, qy, ni);
            float nj = ar1 * qy; nj = fmaf(-ai1, qz, nj); nj = fmaf( aj1, qr, nj); nj = fmaf( ak1, qx, nj);
            float nk = ar1 * qz; nk = fmaf( ai1, qy, nk); nk = fmaf(-aj1, qx, nk); nk = fmaf( ak1, qr, nk);
            ar1 = nr; ai1 = ni; aj1 = nj; ak1 = nk;
        }
    }
    #undef QPAIR

    // ---- normalize + coalesced float2 writes ----
    float rn0 = rsqrtf(fmaf(ar0, ar0, fmaf(ai0, ai0, fmaf(aj0, aj0, fmaf(ak0, ak0, 1e-12f)))));
    float rn1 = rsqrtf(fmaf(ar1, ar1, fmaf(ai1, ai1, fmaf(aj1, aj1, fmaf(ak1, ak1, 1e-12f)))));

    float2* op = (float2*)(out + (size_t)(p0 + pp) * (4 * C_OUT) + obase);
    op[oh]       = make_float2(ar0 * rn0, ar1 * rn1);
    op[64 + oh]  = make_float2(ai0 * rn0, ai1 * rn1);
    op[128 + oh] = make_float2(aj0 * rn0, aj1 * rn1);
    op[192 + oh] = make_float2(ak0 * rn0, ak1 * rn1);
}

extern "C" void kernel_launch(void* const* d_in, const int* in_sizes, int n_in,
                              void* d_out, int out_size) {
    const float* x      = (const float*)d_in[0];
    const float* weight = (const float*)d_in[1];
    const float* bias   = (const float*)d_in[2];
    float* out = (float*)d_out;
    (void)in_sizes; (void)n_in; (void)out_size;

    dim3 grid(NPAIR / PAIRS_PER_BLOCK, 2);   // 512 x 2 = 1024 blocks
    qpu_kernel<<<grid, THREADS>>>(x, weight, bias, out);
}